// round 4
// baseline (speedup 1.0000x reference)
#include <cuda_runtime.h>
#include <cstdint>

// out[b, l] = x[b, perm[b, l]]   (B=1024, L=16384)
// Persistent CTAs (grid = 148 = #SMs on sm_100a), double-buffered row staging
// via cp.async.bulk (TMA) + mbarrier. Removes the 2.31-wave quantization of
// the one-CTA-per-row scheme (R3's DRAM ceiling).

#define THREADS 512
#define NSM 148

__device__ __forceinline__ void mbar_wait(uint32_t mbar, uint32_t parity) {
    uint32_t done;
    asm volatile(
        "{\n\t.reg .pred P;\n\t"
        "mbarrier.try_wait.parity.acquire.cta.shared::cta.b64 P, [%1], %2;\n\t"
        "selp.b32 %0, 1, 0, P;\n\t}"
        : "=r"(done) : "r"(mbar), "r"(parity) : "memory");
    if (!done) {
        asm volatile(
            "{\n\t.reg .pred P;\n\t"
            "W_%=:\n\t"
            "mbarrier.try_wait.parity.acquire.cta.shared::cta.b64 P, [%0], %1, 0x989680;\n\t"
            "@P bra.uni D_%=;\n\t"
            "bra.uni W_%=;\n\t"
            "D_%=:\n\t}"
            :: "r"(mbar), "r"(parity) : "memory");
    }
}

__global__ __launch_bounds__(THREADS, 1)
void interleave_persist_kernel(const float* __restrict__ x,
                               const int* __restrict__ perm,
                               float* __restrict__ out,
                               int L, int B, int grid) {
    extern __shared__ __align__(128) unsigned char smem_raw[];
    float* buf0 = reinterpret_cast<float*>(smem_raw);
    float* buf1 = buf0 + L;
    uint64_t* mbars = reinterpret_cast<uint64_t*>(buf1 + L);

    uint32_t mb[2];
    mb[0] = (uint32_t)__cvta_generic_to_shared(&mbars[0]);
    mb[1] = (uint32_t)__cvta_generic_to_shared(&mbars[1]);
    uint32_t sb[2];
    sb[0] = (uint32_t)__cvta_generic_to_shared(buf0);
    sb[1] = (uint32_t)__cvta_generic_to_shared(buf1);
    float* bufs[2] = {buf0, buf1};

    int tid = threadIdx.x;
    unsigned bytes = (unsigned)L * 4u;

    if (tid == 0) {
        asm volatile("mbarrier.init.shared.b64 [%0], %1;" :: "r"(mb[0]), "r"(1) : "memory");
        asm volatile("mbarrier.init.shared.b64 [%0], %1;" :: "r"(mb[1]), "r"(1) : "memory");
    }
    __syncthreads();

    // Prologue: kick off TMAs for the first two rows of this CTA.
    if (tid == 0) {
        #pragma unroll
        for (int s = 0; s < 2; s++) {
            long long row = (long long)blockIdx.x + (long long)s * grid;
            if (row < B) {
                asm volatile("mbarrier.arrive.expect_tx.shared.b64 _, [%0], %1;"
                             :: "r"(mb[s]), "r"(bytes) : "memory");
                asm volatile("cp.async.bulk.shared::cta.global.mbarrier::complete_tx::bytes "
                             "[%0], [%1], %2, [%3];"
                             :: "r"(sb[s]), "l"(x + row * L), "r"(bytes), "r"(mb[s]) : "memory");
            }
        }
    }

    int i = 0;
    for (long long r = blockIdx.x; r < B; r += grid, i++) {
        int b = i & 1;
        uint32_t ph = (uint32_t)((i >> 1) & 1);
        const float* srow = bufs[b];

        // Prefetch perm for this row while the TMA streams x (L/4 = 8*THREADS).
        const int4* p4 = reinterpret_cast<const int4*>(perm + r * L);
        int4 p[8];
        #pragma unroll
        for (int j = 0; j < 8; j++) p[j] = p4[tid + j * THREADS];

        mbar_wait(mb[b], ph);

        // Gather entire share into registers (frees the buffer for reuse).
        float4 o[8];
        #pragma unroll
        for (int j = 0; j < 8; j++) {
            o[j].x = srow[p[j].x];
            o[j].y = srow[p[j].y];
            o[j].z = srow[p[j].z];
            o[j].w = srow[p[j].w];
        }

        __syncthreads();  // all smem reads of buf[b] done -> safe to refill

        if (tid == 0) {
            long long nr = r + 2LL * grid;
            if (nr < B) {
                asm volatile("mbarrier.arrive.expect_tx.shared.b64 _, [%0], %1;"
                             :: "r"(mb[b]), "r"(bytes) : "memory");
                asm volatile("cp.async.bulk.shared::cta.global.mbarrier::complete_tx::bytes "
                             "[%0], [%1], %2, [%3];"
                             :: "r"(sb[b]), "l"(x + nr * L), "r"(bytes), "r"(mb[b]) : "memory");
            }
        }

        // Coalesced stores overlap the just-issued TMA read.
        float4* o4 = reinterpret_cast<float4*>(out + r * L);
        #pragma unroll
        for (int j = 0; j < 8; j++) o4[tid + j * THREADS] = o[j];
    }
}

extern "C" void kernel_launch(void* const* d_in, const int* in_sizes, int n_in,
                              void* d_out, int out_size) {
    const float* x   = (const float*)d_in[0];
    const int* perm  = (const int*)d_in[1];
    float* out       = (float*)d_out;

    long long total = (long long)in_sizes[1];
    int B = 1024;
    int L = (int)(total / B);

    size_t smem = 2 * (size_t)L * sizeof(float) + 32;  // two row buffers + mbarriers
    cudaFuncSetAttribute(interleave_persist_kernel,
                         cudaFuncAttributeMaxDynamicSharedMemorySize, (int)smem);

    interleave_persist_kernel<<<NSM, THREADS, smem>>>(x, perm, out, L, B, NSM);
}